// round 5
// baseline (speedup 1.0000x reference)
#include <cuda_runtime.h>
#include <math.h>

#define BB 2
#define SS 2048
#define EE 1024
#define HH 16
#define DD 64
#define MROWS (BB*SS)            // 4096
#define QK (SS*SS)               // 4194304 per (b,h)

// Scratch (allocation-free rule: __device__ globals)
__device__ float g_q [MROWS*EE];
__device__ float g_k [MROWS*EE];
__device__ float g_v [MROWS*EE];
__device__ float g_ao[MROWS*EE];
__device__ float g_p [134217728];   // [B,H,S,S] probs, 536 MB

// ---------------------------------------------------------------------------
// tf32 helpers
// ---------------------------------------------------------------------------
__device__ __forceinline__ unsigned f2t(float f){
    unsigned r; asm("cvt.rna.tf32.f32 %0, %1;" : "=r"(r) : "f"(f)); return r;
}
__device__ __forceinline__ void mma8(float* c, const unsigned* a, const unsigned* b){
    asm volatile("mma.sync.aligned.m16n8k8.row.col.f32.tf32.tf32.f32 "
        "{%0,%1,%2,%3},{%4,%5,%6,%7},{%8,%9},{%0,%1,%2,%3};"
        : "+f"(c[0]),"+f"(c[1]),"+f"(c[2]),"+f"(c[3])
        : "r"(a[0]),"r"(a[1]),"r"(a[2]),"r"(a[3]),"r"(b[0]),"r"(b[1]));
}
// Permuted k-layout: within each 8-col group, col j stored at (j&3)*2+(j>>2).
// Then thread t's fragment pair (t, t+4) sits at (2t, 2t+1) -> one LDS.64.
__device__ __forceinline__ int pcol(int c){   // c multiple of 4; base of 4-elem
    return (c & ~7) + ((c & 4) >> 2);         // elems at base+0,2,4,6
}
__device__ __forceinline__ int prow(int r){   // single k index permute
    return (r & ~7) + ((r & 3) << 1) + ((r & 7) >> 2);
}

// ---------------------------------------------------------------------------
// Projection GEMM: C[4096,1024] = A[4096,1024] @ W[1024,1024]^T + b
// grid.z selects among up to 3 (W,b,C) sets -> fused QKV in one launch.
// BM=128 BN=128 BK=16, 8 warps (4m x 2n), warp 32x64, double-buffered.
// ---------------------------------------------------------------------------
__global__ void __launch_bounds__(256,2)
proj_tf32(const float* __restrict__ A,
          const float* __restrict__ W0,const float* __restrict__ W1,const float* __restrict__ W2,
          const float* __restrict__ b0,const float* __restrict__ b1,const float* __restrict__ b2,
          float* __restrict__ C0,float* __restrict__ C1,float* __restrict__ C2)
{
    constexpr int BK=16, LD=BK+4;
    __shared__ unsigned As[2][128*LD], Bs[2][128*LD];
    const int z=blockIdx.z;
    const float* W   = z==0?W0:(z==1?W1:W2);
    const float* bias= z==0?b0:(z==1?b1:b2);
    float*       C   = z==0?C0:(z==1?C1:C2);

    const int tid=threadIdx.x, lane=tid&31, wid=tid>>5;
    const int g=lane>>2, t=lane&3;
    const int wm=wid>>1, wn=wid&1;
    const int m0=blockIdx.y*128, n0=blockIdx.x*128;
    const int lr=tid>>2, lc=(tid&3)<<2, pb=pcol(lc);

    float4 pa[2], pbv[2];
    auto ldg=[&](int kt){
#pragma unroll
        for(int j=0;j<2;j++){
            pa [j]=*(const float4*)(A+(long)(m0+lr+j*64)*EE+kt*BK+lc);
            pbv[j]=*(const float4*)(W+(long)(n0+lr+j*64)*EE+kt*BK+lc);
        }
    };
    auto sts=[&](int buf){
#pragma unroll
        for(int j=0;j<2;j++){
            int r=lr+j*64;
            As[buf][r*LD+pb  ]=f2t(pa [j].x); As[buf][r*LD+pb+2]=f2t(pa [j].y);
            As[buf][r*LD+pb+4]=f2t(pa [j].z); As[buf][r*LD+pb+6]=f2t(pa [j].w);
            Bs[buf][r*LD+pb  ]=f2t(pbv[j].x); Bs[buf][r*LD+pb+2]=f2t(pbv[j].y);
            Bs[buf][r*LD+pb+4]=f2t(pbv[j].z); Bs[buf][r*LD+pb+6]=f2t(pbv[j].w);
        }
    };

    float acc[2][8][4];
#pragma unroll
    for(int i=0;i<2;i++)
#pragma unroll
        for(int j=0;j<8;j++)
#pragma unroll
            for(int k=0;k<4;k++) acc[i][j][k]=0.f;

    const int NT=EE/BK;   // 64
    ldg(0); sts(0); __syncthreads();
    for(int kt=0;kt<NT;kt++){
        const int buf=kt&1;
        if(kt+1<NT) ldg(kt+1);
#pragma unroll
        for(int kk=0;kk<2;kk++){
            unsigned af[2][4], bf[8][2];
#pragma unroll
            for(int mi=0;mi<2;mi++){
                const int rb=wm*32+mi*16;
                uint2 u0=*(const uint2*)&As[buf][(rb+g  )*LD+kk*8+2*t];
                uint2 u1=*(const uint2*)&As[buf][(rb+g+8)*LD+kk*8+2*t];
                af[mi][0]=u0.x; af[mi][1]=u1.x; af[mi][2]=u0.y; af[mi][3]=u1.y;
            }
#pragma unroll
            for(int nj=0;nj<8;nj++){
                uint2 ub=*(const uint2*)&Bs[buf][(wn*64+nj*8+g)*LD+kk*8+2*t];
                bf[nj][0]=ub.x; bf[nj][1]=ub.y;
            }
#pragma unroll
            for(int mi=0;mi<2;mi++)
#pragma unroll
                for(int nj=0;nj<8;nj++)
                    mma8(acc[mi][nj],af[mi],bf[nj]);
        }
        if(kt+1<NT){ sts((kt+1)&1); __syncthreads(); }
    }
#pragma unroll
    for(int mi=0;mi<2;mi++){
        const int r0=m0+wm*32+mi*16+g;
#pragma unroll
        for(int nj=0;nj<8;nj++){
            const int col=n0+wn*64+nj*8+2*t;
            float c0=bias[col], c1=bias[col+1];
            float2 v0={acc[mi][nj][0]+c0, acc[mi][nj][1]+c1};
            float2 v1={acc[mi][nj][2]+c0, acc[mi][nj][3]+c1};
            *(float2*)(C+(long)r0*EE+col)=v0;
            *(float2*)(C+(long)(r0+8)*EE+col)=v1;
        }
    }
}

// ---------------------------------------------------------------------------
// Fused scores + heads-softmax, double-buffered over heads.
// CTA = (b, q-tile 64, k-tile 32); 8 warps (2m x 4n), warp 32q x 8k.
// acc holds all 16 heads -> cross-head softmax in registers; P written once.
// ---------------------------------------------------------------------------
__global__ void __launch_bounds__(256,1)
scores_smax(const float* __restrict__ Q, const float* __restrict__ Kmat,
            float* __restrict__ P)
{
    constexpr int LD=72;   // 64 + 8 pad (stride mod 32 words == 8)
    __shared__ unsigned Qs[2][64*LD], Ks[2][32*LD];
    const int tid=threadIdx.x, lane=tid&31, wid=tid>>5;
    const int g=lane>>2, t=lane&3;
    const int wm=wid>>2, wn=wid&3;
    const int b=blockIdx.z, q0=blockIdx.y*64, k0=blockIdx.x*32;
    const float* Qb=Q   +((long)b*SS+q0)*EE;
    const float* Kb=Kmat+((long)b*SS+k0)*EE;

    float4 pq[4], pk[2];
    auto ldg=[&](int h){
#pragma unroll
        for(int i=0;i<4;i++){ int idx=tid+i*256, r=idx>>4, c=(idx&15)<<2;
            pq[i]=*(const float4*)(Qb+(long)r*EE+h*DD+c); }
#pragma unroll
        for(int i=0;i<2;i++){ int idx=tid+i*256, r=idx>>4, c=(idx&15)<<2;
            pk[i]=*(const float4*)(Kb+(long)r*EE+h*DD+c); }
    };
    auto sts=[&](int buf){
#pragma unroll
        for(int i=0;i<4;i++){ int idx=tid+i*256, r=idx>>4, c=(idx&15)<<2, bs=pcol(c);
            Qs[buf][r*LD+bs  ]=f2t(pq[i].x); Qs[buf][r*LD+bs+2]=f2t(pq[i].y);
            Qs[buf][r*LD+bs+4]=f2t(pq[i].z); Qs[buf][r*LD+bs+6]=f2t(pq[i].w); }
#pragma unroll
        for(int i=0;i<2;i++){ int idx=tid+i*256, r=idx>>4, c=(idx&15)<<2, bs=pcol(c);
            Ks[buf][r*LD+bs  ]=f2t(pk[i].x); Ks[buf][r*LD+bs+2]=f2t(pk[i].y);
            Ks[buf][r*LD+bs+4]=f2t(pk[i].z); Ks[buf][r*LD+bs+6]=f2t(pk[i].w); }
    };

    float acc[HH][2][4];
#pragma unroll
    for(int h=0;h<HH;h++)
#pragma unroll
        for(int mi=0;mi<2;mi++)
#pragma unroll
            for(int f=0;f<4;f++) acc[h][mi][f]=0.f;

    ldg(0); sts(0); __syncthreads();
#pragma unroll
    for(int h=0;h<HH;h++){
        const int buf=h&1;
        if(h+1<HH) ldg(h+1);
#pragma unroll
        for(int kk=0;kk<8;kk++){
            uint2 ub=*(const uint2*)&Ks[buf][(wn*8+g)*LD+kk*8+2*t];
            unsigned bfr[2]={ub.x,ub.y};
#pragma unroll
            for(int mi=0;mi<2;mi++){
                const int rb=wm*32+mi*16;
                uint2 u0=*(const uint2*)&Qs[buf][(rb+g  )*LD+kk*8+2*t];
                uint2 u1=*(const uint2*)&Qs[buf][(rb+g+8)*LD+kk*8+2*t];
                unsigned afr[4]={u0.x,u1.x,u0.y,u1.y};
                mma8(acc[h][mi],afr,bfr);
            }
        }
        if(h+1<HH){ sts(1-buf); __syncthreads(); }
    }

    // softmax across the 16 heads, per fragment slot (scale 1/8 first)
#pragma unroll
    for(int mi=0;mi<2;mi++)
#pragma unroll
    for(int f=0;f<4;f++){
        float m=-1e30f;
#pragma unroll
        for(int h=0;h<HH;h++){ acc[h][mi][f]*=0.125f; m=fmaxf(m,acc[h][mi][f]); }
        float s=0.f;
#pragma unroll
        for(int h=0;h<HH;h++){ float e=__expf(acc[h][mi][f]-m); acc[h][mi][f]=e; s+=e; }
        const float inv=1.f/s;
#pragma unroll
        for(int h=0;h<HH;h++) acc[h][mi][f]*=inv;
    }

#pragma unroll
    for(int h=0;h<HH;h++){
        float* Ph=P+((long)(b*HH+h))*QK;
#pragma unroll
        for(int mi=0;mi<2;mi++){
            const int r0=q0+wm*32+mi*16+g;
            const int col=k0+wn*8+2*t;
            float2 v0={acc[h][mi][0],acc[h][mi][1]};
            float2 v1={acc[h][mi][2],acc[h][mi][3]};
            *(float2*)(Ph+(long)r0*SS+col)=v0;
            *(float2*)(Ph+(long)(r0+8)*SS+col)=v1;
        }
    }
}

// ---------------------------------------------------------------------------
// P @ V per (b,h): O[2048,64] = P[2048,2048] @ V_bh[2048,64]
// BM=128 BN=64 BK=16, 8 warps (4m x 2n), warp 32x32, double-buffered.
// ---------------------------------------------------------------------------
__global__ void __launch_bounds__(256,2)
pv_tf32(const float* __restrict__ P, const float* __restrict__ V,
        float* __restrict__ O)
{
    constexpr int BK=16, LD=BK+4;
    __shared__ unsigned As[2][128*LD], Bs[2][64*LD];
    const int tid=threadIdx.x, lane=tid&31, wid=tid>>5;
    const int g=lane>>2, t=lane&3;
    const int wm=wid>>1, wn=wid&1;
    const int z=blockIdx.z, b=z/HH, h=z%HH;
    const int m0=blockIdx.y*128;
    const float* Pb=P+((long)(b*HH+h))*QK;
    const float* Vb=V+(long)b*SS*EE+h*DD;
    float*       Ob=O+(long)b*SS*EE+h*DD;

    float4 pa[2], pv;
    auto ldg=[&](int kt){
#pragma unroll
        for(int j=0;j<2;j++){
            int idx=tid+j*256, r=idx>>2, c=(idx&3)<<2;
            pa[j]=*(const float4*)(Pb+(long)(m0+r)*SS+kt*BK+c);
        }
        { int r=tid>>4, c=(tid&15)<<2;
          pv=*(const float4*)(Vb+(long)(kt*BK+r)*EE+c); }
    };
    auto sts=[&](int buf){
#pragma unroll
        for(int j=0;j<2;j++){
            int idx=tid+j*256, r=idx>>2, c=(idx&3)<<2, bs=pcol(c);
            As[buf][r*LD+bs  ]=f2t(pa[j].x); As[buf][r*LD+bs+2]=f2t(pa[j].y);
            As[buf][r*LD+bs+4]=f2t(pa[j].z); As[buf][r*LD+bs+6]=f2t(pa[j].w);
        }
        { int r=tid>>4, c=(tid&15)<<2, rp=prow(r);   // transpose V -> Bs[d][k']
          Bs[buf][(c+0)*LD+rp]=f2t(pv.x); Bs[buf][(c+1)*LD+rp]=f2t(pv.y);
          Bs[buf][(c+2)*LD+rp]=f2t(pv.z); Bs[buf][(c+3)*LD+rp]=f2t(pv.w); }
    };

    float acc[2][4][4];
#pragma unroll
    for(int i=0;i<2;i++)
#pragma unroll
        for(int j=0;j<4;j++)
#pragma unroll
            for(int k=0;k<4;k++) acc[i][j][k]=0.f;

    const int NT=SS/BK;   // 128
    ldg(0); sts(0); __syncthreads();
    for(int kt=0;kt<NT;kt++){
        const int buf=kt&1;
        if(kt+1<NT) ldg(kt+1);
#pragma unroll
        for(int kk=0;kk<2;kk++){
            unsigned af[2][4], bf[4][2];
#pragma unroll
            for(int mi=0;mi<2;mi++){
                const int rb=wm*32+mi*16;
                uint2 u0=*(const uint2*)&As[buf][(rb+g  )*LD+kk*8+2*t];
                uint2 u1=*(const uint2*)&As[buf][(rb+g+8)*LD+kk*8+2*t];
                af[mi][0]=u0.x; af[mi][1]=u1.x; af[mi][2]=u0.y; af[mi][3]=u1.y;
            }
#pragma unroll
            for(int nj=0;nj<4;nj++){
                uint2 ub=*(const uint2*)&Bs[buf][(wn*32+nj*8+g)*LD+kk*8+2*t];
                bf[nj][0]=ub.x; bf[nj][1]=ub.y;
            }
#pragma unroll
            for(int mi=0;mi<2;mi++)
#pragma unroll
                for(int nj=0;nj<4;nj++)
                    mma8(acc[mi][nj],af[mi],bf[nj]);
        }
        if(kt+1<NT){ sts((kt+1)&1); __syncthreads(); }
    }
#pragma unroll
    for(int mi=0;mi<2;mi++){
        const int r0=m0+wm*32+mi*16+g;
#pragma unroll
        for(int nj=0;nj<4;nj++){
            const int col=wn*32+nj*8+2*t;
            float2 v0={acc[mi][nj][0],acc[mi][nj][1]};
            float2 v1={acc[mi][nj][2],acc[mi][nj][3]};
            *(float2*)(Ob+(long)r0*EE+col)=v0;
            *(float2*)(Ob+(long)(r0+8)*EE+col)=v1;
        }
    }
}

// ---------------------------------------------------------------------------
extern "C" void kernel_launch(void* const* d_in, const int* in_sizes, int n_in,
                              void* d_out, int out_size)
{
    const float* x  = (const float*)d_in[0];
    const float* Wq = (const float*)d_in[1];
    const float* bq = (const float*)d_in[2];
    const float* Wk = (const float*)d_in[3];
    const float* bk = (const float*)d_in[4];
    const float* Wv = (const float*)d_in[5];
    const float* bv = (const float*)d_in[6];
    const float* Wo = (const float*)d_in[7];
    const float* bo = (const float*)d_in[8];
    float* out = (float*)d_out;

    float *q,*k,*v,*ao,*p;
    cudaGetSymbolAddress((void**)&q,  g_q);
    cudaGetSymbolAddress((void**)&k,  g_k);
    cudaGetSymbolAddress((void**)&v,  g_v);
    cudaGetSymbolAddress((void**)&ao, g_ao);
    cudaGetSymbolAddress((void**)&p,  g_p);

    dim3 blk(256);

    // Fused Q/K/V projections (grid.z picks the weight set)
    dim3 gqkv(EE/128, MROWS/128, 3);
    proj_tf32<<<gqkv,blk>>>(x, Wq,Wk,Wv, bq,bk,bv, q,k,v);

    dim3 gsc(SS/32, SS/64, BB);          // (64,32,2)
    scores_smax<<<gsc,blk>>>(q, k, p);

    dim3 gpv(1, SS/128, BB*HH);          // (1,16,32)
    pv_tf32<<<gpv,blk>>>(p, v, ao);

    dim3 go(EE/128, MROWS/128, 1);
    proj_tf32<<<go,blk>>>(ao, Wo,Wo,Wo, bo,bo,bo, out,out,out);
}

// round 6
// speedup vs baseline: 1.1568x; 1.1568x over previous
#include <cuda_runtime.h>
#include <math.h>

#define BB 2
#define SS 2048
#define EE 1024
#define HH 16
#define DD 64
#define MROWS (BB*SS)            // 4096
#define QK (SS*SS)               // 4194304 per (b,h)

// Scratch (allocation-free rule: __device__ globals)
__device__ float g_q [MROWS*EE];   // tf32-bit payload
__device__ float g_k [MROWS*EE];   // tf32-bit payload
__device__ float g_v [MROWS*EE];   // tf32-bit payload
__device__ float g_ao[MROWS*EE];   // tf32-bit payload
__device__ float g_p [134217728];  // [B,H,S,S] probs, tf32-bit payload

// ---------------------------------------------------------------------------
// helpers
// ---------------------------------------------------------------------------
__device__ __forceinline__ unsigned f2t(float f){
    unsigned r; asm("cvt.rna.tf32.f32 %0, %1;" : "=r"(r) : "f"(f)); return r;
}
__device__ __forceinline__ void mma8(float* c, const unsigned* a, const unsigned* b){
    asm volatile("mma.sync.aligned.m16n8k8.row.col.f32.tf32.tf32.f32 "
        "{%0,%1,%2,%3},{%4,%5,%6,%7},{%8,%9},{%0,%1,%2,%3};"
        : "+f"(c[0]),"+f"(c[1]),"+f"(c[2]),"+f"(c[3])
        : "r"(a[0]),"r"(a[1]),"r"(a[2]),"r"(a[3]),"r"(b[0]),"r"(b[1]));
}
#define CPA16(dst,src) asm volatile("cp.async.cg.shared.global [%0],[%1],16;"::"r"(dst),"l"(src))
#define CPA_COMMIT()   asm volatile("cp.async.commit_group;")
#define CPA_WAIT0()    asm volatile("cp.async.wait_group 0;" ::: "memory")
// Permuted k-layout (register-staged proj only): col j -> (j&3)*2+(j>>2)
__device__ __forceinline__ int pcol(int c){ return (c & ~7) + ((c & 4) >> 2); }

// ---------------------------------------------------------------------------
// Projection GEMM: C[4096,1024] = A[4096,1024] @ W[1024,1024]^T + b
// grid.z selects (W,b,C). CVT_OUT=1 -> store rna'd tf32 bit patterns.
// ---------------------------------------------------------------------------
template<int CVT_OUT>
__global__ void __launch_bounds__(256,2)
proj_tf32(const float* __restrict__ A,
          const float* __restrict__ W0,const float* __restrict__ W1,const float* __restrict__ W2,
          const float* __restrict__ b0,const float* __restrict__ b1,const float* __restrict__ b2,
          float* __restrict__ C0,float* __restrict__ C1,float* __restrict__ C2)
{
    constexpr int BK=16, LD=BK+4;
    __shared__ unsigned As[2][128*LD], Bs[2][128*LD];
    const int z=blockIdx.z;
    const float* W   = z==0?W0:(z==1?W1:W2);
    const float* bias= z==0?b0:(z==1?b1:b2);
    float*       C   = z==0?C0:(z==1?C1:C2);

    const int tid=threadIdx.x, lane=tid&31, wid=tid>>5;
    const int g=lane>>2, t=lane&3;
    const int wm=wid>>1, wn=wid&1;
    const int m0=blockIdx.y*128, n0=blockIdx.x*128;
    const int lr=tid>>2, lc=(tid&3)<<2, pb=pcol(lc);

    float4 pa[2], pbv[2];
    auto ldg=[&](int kt){
#pragma unroll
        for(int j=0;j<2;j++){
            pa [j]=*(const float4*)(A+(long)(m0+lr+j*64)*EE+kt*BK+lc);
            pbv[j]=*(const float4*)(W+(long)(n0+lr+j*64)*EE+kt*BK+lc);
        }
    };
    auto sts=[&](int buf){
#pragma unroll
        for(int j=0;j<2;j++){
            int r=lr+j*64;
            As[buf][r*LD+pb  ]=f2t(pa [j].x); As[buf][r*LD+pb+2]=f2t(pa [j].y);
            As[buf][r*LD+pb+4]=f2t(pa [j].z); As[buf][r*LD+pb+6]=f2t(pa [j].w);
            Bs[buf][r*LD+pb  ]=f2t(pbv[j].x); Bs[buf][r*LD+pb+2]=f2t(pbv[j].y);
            Bs[buf][r*LD+pb+4]=f2t(pbv[j].z); Bs[buf][r*LD+pb+6]=f2t(pbv[j].w);
        }
    };

    float acc[2][8][4];
#pragma unroll
    for(int i=0;i<2;i++)
#pragma unroll
        for(int j=0;j<8;j++)
#pragma unroll
            for(int k=0;k<4;k++) acc[i][j][k]=0.f;

    const int NT=EE/BK;   // 64
    ldg(0); sts(0); __syncthreads();
    for(int kt=0;kt<NT;kt++){
        const int buf=kt&1;
        if(kt+1<NT) ldg(kt+1);
#pragma unroll
        for(int kk=0;kk<2;kk++){
            unsigned af[2][4], bf[8][2];
#pragma unroll
            for(int mi=0;mi<2;mi++){
                const int rb=wm*32+mi*16;
                uint2 u0=*(const uint2*)&As[buf][(rb+g  )*LD+kk*8+2*t];
                uint2 u1=*(const uint2*)&As[buf][(rb+g+8)*LD+kk*8+2*t];
                af[mi][0]=u0.x; af[mi][1]=u1.x; af[mi][2]=u0.y; af[mi][3]=u1.y;
            }
#pragma unroll
            for(int nj=0;nj<8;nj++){
                uint2 ub=*(const uint2*)&Bs[buf][(wn*64+nj*8+g)*LD+kk*8+2*t];
                bf[nj][0]=ub.x; bf[nj][1]=ub.y;
            }
#pragma unroll
            for(int mi=0;mi<2;mi++)
#pragma unroll
                for(int nj=0;nj<8;nj++)
                    mma8(acc[mi][nj],af[mi],bf[nj]);
        }
        if(kt+1<NT){ sts((kt+1)&1); __syncthreads(); }
    }
#pragma unroll
    for(int mi=0;mi<2;mi++){
        const int r0=m0+wm*32+mi*16+g;
#pragma unroll
        for(int nj=0;nj<8;nj++){
            const int col=n0+wn*64+nj*8+2*t;
            float c0=bias[col], c1=bias[col+1];
            float o00=acc[mi][nj][0]+c0, o01=acc[mi][nj][1]+c1;
            float o10=acc[mi][nj][2]+c0, o11=acc[mi][nj][3]+c1;
            float2 v0, v1;
            if(CVT_OUT){
                v0.x=__uint_as_float(f2t(o00)); v0.y=__uint_as_float(f2t(o01));
                v1.x=__uint_as_float(f2t(o10)); v1.y=__uint_as_float(f2t(o11));
            } else { v0.x=o00; v0.y=o01; v1.x=o10; v1.y=o11; }
            *(float2*)(C+(long)r0*EE+col)=v0;
            *(float2*)(C+(long)(r0+8)*EE+col)=v1;
        }
    }
}

// ---------------------------------------------------------------------------
// Fused scores + heads-softmax. Inputs are pre-converted tf32 bits ->
// cp.async tiles directly to smem (no staging regs, no cvt).
// CTA = (b, q-tile 64, k-tile 32); 8 warps (2m x 4n), warp 32q x 8k.
// Double-buffered over heads; P written once as tf32 bits.
// ---------------------------------------------------------------------------
__global__ void __launch_bounds__(256,1)
scores_smax(const float* __restrict__ Q, const float* __restrict__ Kmat,
            float* __restrict__ P)
{
    constexpr int LD=68;   // 64+4: conflict-free scalar frag loads (8g+... -> 4g+t)
    __shared__ unsigned Qs[2][64*LD], Ks[2][32*LD];
    const int tid=threadIdx.x, lane=tid&31, wid=tid>>5;
    const int g=lane>>2, t=lane&3;
    const int wm=wid>>2, wn=wid&3;
    const int b=blockIdx.z, q0=blockIdx.y*64, k0=blockIdx.x*32;
    const float* Qb=Q   +((long)b*SS+q0)*EE;
    const float* Kb=Kmat+((long)b*SS+k0)*EE;

    const unsigned qs0=(unsigned)__cvta_generic_to_shared(&Qs[0][0]);
    const unsigned qs1=(unsigned)__cvta_generic_to_shared(&Qs[1][0]);
    const unsigned ks0=(unsigned)__cvta_generic_to_shared(&Ks[0][0]);
    const unsigned ks1=(unsigned)__cvta_generic_to_shared(&Ks[1][0]);

    auto issue=[&](int h,int buf){
        const unsigned qb = buf? qs1:qs0;
        const unsigned kb = buf? ks1:ks0;
#pragma unroll
        for(int i=0;i<4;i++){ int idx=tid+i*256, r=idx>>4, c=(idx&15)<<2;
            CPA16(qb+(r*LD+c)*4, Qb+(long)r*EE+h*DD+c); }
#pragma unroll
        for(int i=0;i<2;i++){ int idx=tid+i*256, r=idx>>4, c=(idx&15)<<2;
            CPA16(kb+(r*LD+c)*4, Kb+(long)r*EE+h*DD+c); }
    };

    float acc[HH][2][4];
#pragma unroll
    for(int h=0;h<HH;h++)
#pragma unroll
        for(int mi=0;mi<2;mi++)
#pragma unroll
            for(int f=0;f<4;f++) acc[h][mi][f]=0.f;

    issue(0,0); CPA_COMMIT(); CPA_WAIT0(); __syncthreads();
#pragma unroll
    for(int h=0;h<HH;h++){
        const int buf=h&1;
        if(h+1<HH){ issue(h+1,buf^1); CPA_COMMIT(); }
        const unsigned* Qsb=Qs[buf];
        const unsigned* Ksb=Ks[buf];
#pragma unroll
        for(int kk=0;kk<8;kk++){
            unsigned bfr[2];
            bfr[0]=Ksb[(wn*8+g)*LD+kk*8+t  ];
            bfr[1]=Ksb[(wn*8+g)*LD+kk*8+t+4];
#pragma unroll
            for(int mi=0;mi<2;mi++){
                const int rb=wm*32+mi*16;
                unsigned afr[4];
                afr[0]=Qsb[(rb+g  )*LD+kk*8+t  ];
                afr[1]=Qsb[(rb+g+8)*LD+kk*8+t  ];
                afr[2]=Qsb[(rb+g  )*LD+kk*8+t+4];
                afr[3]=Qsb[(rb+g+8)*LD+kk*8+t+4];
                mma8(acc[h][mi],afr,bfr);
            }
        }
        if(h+1<HH){ CPA_WAIT0(); __syncthreads(); }
    }

    // softmax across the 16 heads, per fragment slot (scale 1/8 first)
#pragma unroll
    for(int mi=0;mi<2;mi++)
#pragma unroll
    for(int f=0;f<4;f++){
        float m=-1e30f;
#pragma unroll
        for(int h=0;h<HH;h++){ acc[h][mi][f]*=0.125f; m=fmaxf(m,acc[h][mi][f]); }
        float s=0.f;
#pragma unroll
        for(int h=0;h<HH;h++){ float e=__expf(acc[h][mi][f]-m); acc[h][mi][f]=e; s+=e; }
        const float inv=1.f/s;
#pragma unroll
        for(int h=0;h<HH;h++) acc[h][mi][f]*=inv;
    }

#pragma unroll
    for(int h=0;h<HH;h++){
        float* Ph=P+((long)(b*HH+h))*QK;
#pragma unroll
        for(int mi=0;mi<2;mi++){
            const int r0=q0+wm*32+mi*16+g;
            const int col=k0+wn*8+2*t;
            float2 v0={__uint_as_float(f2t(acc[h][mi][0])),
                       __uint_as_float(f2t(acc[h][mi][1]))};
            float2 v1={__uint_as_float(f2t(acc[h][mi][2])),
                       __uint_as_float(f2t(acc[h][mi][3]))};
            *(float2*)(Ph+(long)r0*SS+col)=v0;
            *(float2*)(Ph+(long)(r0+8)*SS+col)=v1;
        }
    }
}

// ---------------------------------------------------------------------------
// P @ V per (b,h): O[2048,64] = P[2048,2048] @ V_bh[2048,64]
// P and V are pre-converted tf32 bits -> cp.async both operands.
// BM=128 BN=64 BK=16, 8 warps (4m x 2n). V kept [k][d] (LD=72, conflict-free).
// ---------------------------------------------------------------------------
__global__ void __launch_bounds__(256,2)
pv_tf32(const float* __restrict__ P, const float* __restrict__ V,
        float* __restrict__ O)
{
    constexpr int BK=16, LDA=BK+4 /*20*/, LDV=72;
    __shared__ unsigned As[2][128*LDA], Vs[2][BK*LDV];
    const int tid=threadIdx.x, lane=tid&31, wid=tid>>5;
    const int g=lane>>2, t=lane&3;
    const int wm=wid>>1, wn=wid&1;
    const int z=blockIdx.z, b=z/HH, h=z%HH;
    const int m0=blockIdx.y*128;
    const float* Pb=P+((long)(b*HH+h))*QK;
    const float* Vb=V+(long)b*SS*EE+h*DD;
    float*       Ob=O+(long)b*SS*EE+h*DD;

    const unsigned as0=(unsigned)__cvta_generic_to_shared(&As[0][0]);
    const unsigned as1=(unsigned)__cvta_generic_to_shared(&As[1][0]);
    const unsigned vs0=(unsigned)__cvta_generic_to_shared(&Vs[0][0]);
    const unsigned vs1=(unsigned)__cvta_generic_to_shared(&Vs[1][0]);

    auto issue=[&](int kt,int buf){
        const unsigned ab = buf? as1:as0;
        const unsigned vb = buf? vs1:vs0;
#pragma unroll
        for(int i=0;i<2;i++){ int idx=tid+i*256, r=idx>>2, c=(idx&3)<<2;
            CPA16(ab+(r*LDA+c)*4, Pb+(long)(m0+r)*SS+kt*BK+c); }
        { int r=tid>>4, c=(tid&15)<<2;
          CPA16(vb+(r*LDV+c)*4, Vb+(long)(kt*BK+r)*EE+c); }
    };

    float acc[2][4][4];
#pragma unroll
    for(int i=0;i<2;i++)
#pragma unroll
        for(int j=0;j<4;j++)
#pragma unroll
            for(int k=0;k<4;k++) acc[i][j][k]=0.f;

    const int NT=SS/BK;   // 128
    issue(0,0); CPA_COMMIT(); CPA_WAIT0(); __syncthreads();
    for(int kt=0;kt<NT;kt++){
        const int buf=kt&1;
        if(kt+1<NT){ issue(kt+1,buf^1); CPA_COMMIT(); }
        const unsigned* Asb=As[buf];
        const unsigned* Vsb=Vs[buf];
#pragma unroll
        for(int kk=0;kk<2;kk++){
            unsigned af[2][4], bf[4][2];
#pragma unroll
            for(int mi=0;mi<2;mi++){
                const int rb=wm*32+mi*16;
                af[mi][0]=Asb[(rb+g  )*LDA+kk*8+t  ];
                af[mi][1]=Asb[(rb+g+8)*LDA+kk*8+t  ];
                af[mi][2]=Asb[(rb+g  )*LDA+kk*8+t+4];
                af[mi][3]=Asb[(rb+g+8)*LDA+kk*8+t+4];
            }
#pragma unroll
            for(int nj=0;nj<4;nj++){
                const int d=wn*32+nj*8+g;
                bf[nj][0]=Vsb[(kk*8+t  )*LDV+d];
                bf[nj][1]=Vsb[(kk*8+t+4)*LDV+d];
            }
#pragma unroll
            for(int mi=0;mi<2;mi++)
#pragma unroll
                for(int nj=0;nj<4;nj++)
                    mma8(acc[mi][nj],af[mi],bf[nj]);
        }
        if(kt+1<NT){ CPA_WAIT0(); __syncthreads(); }
    }
#pragma unroll
    for(int mi=0;mi<2;mi++){
        const int r0=m0+wm*32+mi*16+g;
#pragma unroll
        for(int nj=0;nj<4;nj++){
            const int col=wn*32+nj*8+2*t;
            float2 v0={__uint_as_float(f2t(acc[mi][nj][0])),
                       __uint_as_float(f2t(acc[mi][nj][1]))};
            float2 v1={__uint_as_float(f2t(acc[mi][nj][2])),
                       __uint_as_float(f2t(acc[mi][nj][3]))};
            *(float2*)(Ob+(long)r0*EE+col)=v0;
            *(float2*)(Ob+(long)(r0+8)*EE+col)=v1;
        }
    }
}

// ---------------------------------------------------------------------------
extern "C" void kernel_launch(void* const* d_in, const int* in_sizes, int n_in,
                              void* d_out, int out_size)
{
    const float* x  = (const float*)d_in[0];
    const float* Wq = (const float*)d_in[1];
    const float* bq = (const float*)d_in[2];
    const float* Wk = (const float*)d_in[3];
    const float* bk = (const float*)d_in[4];
    const float* Wv = (const float*)d_in[5];
    const float* bv = (const float*)d_in[6];
    const float* Wo = (const float*)d_in[7];
    const float* bo = (const float*)d_in[8];
    float* out = (float*)d_out;

    float *q,*k,*v,*ao,*p;
    cudaGetSymbolAddress((void**)&q,  g_q);
    cudaGetSymbolAddress((void**)&k,  g_k);
    cudaGetSymbolAddress((void**)&v,  g_v);
    cudaGetSymbolAddress((void**)&ao, g_ao);
    cudaGetSymbolAddress((void**)&p,  g_p);

    dim3 blk(256);

    // Fused Q/K/V projections -> tf32-bit outputs
    dim3 gqkv(EE/128, MROWS/128, 3);
    proj_tf32<1><<<gqkv,blk>>>(x, Wq,Wk,Wv, bq,bk,bv, q,k,v);

    dim3 gsc(SS/32, SS/64, BB);          // (64,32,2)
    scores_smax<<<gsc,blk>>>(q, k, p);

    dim3 gpv(1, SS/128, BB*HH);          // (1,16,32)
    pv_tf32<<<gpv,blk>>>(p, v, ao);

    // Output projection -> fp32
    dim3 go(EE/128, MROWS/128, 1);
    proj_tf32<0><<<go,blk>>>(ao, Wo,Wo,Wo, bo,bo,bo, out,out,out);
}

// round 11
// speedup vs baseline: 1.3615x; 1.1769x over previous
#include <cuda_runtime.h>
#include <cuda_fp16.h>
#include <math.h>

#define BB 2
#define SS 2048
#define EE 1024
#define HH 16
#define DD 64
#define MROWS (BB*SS)            // 4096
#define QK (SS*SS)               // 4194304 per (b,h)

// Scratch (allocation-free rule: __device__ globals), fp16 payloads
__device__ __half g_xh [MROWS*EE];
__device__ __half g_wqh[EE*EE];
__device__ __half g_wkh[EE*EE];
__device__ __half g_wvh[EE*EE];
__device__ __half g_woh[EE*EE];
__device__ __half g_q  [MROWS*EE];
__device__ __half g_k  [MROWS*EE];
__device__ __half g_vt [(long)BB*EE*SS];   // V transposed: [b][e][s]
__device__ __half g_ao [MROWS*EE];
__device__ __half g_p  [134217728];        // [B,H,S,S] probs (256 MB)

// ---------------------------------------------------------------------------
// helpers
// ---------------------------------------------------------------------------
__device__ __forceinline__ void mma16(float* c, const unsigned* a, const unsigned* b){
    asm volatile("mma.sync.aligned.m16n8k16.row.col.f32.f16.f16.f32 "
        "{%0,%1,%2,%3},{%4,%5,%6,%7},{%8,%9},{%0,%1,%2,%3};"
        : "+f"(c[0]),"+f"(c[1]),"+f"(c[2]),"+f"(c[3])
        : "r"(a[0]),"r"(a[1]),"r"(a[2]),"r"(a[3]),"r"(b[0]),"r"(b[1]));
}
#define CPA16(dst,src) asm volatile("cp.async.cg.shared.global [%0],[%1],16;"::"r"(dst),"l"(src))
#define CPA_COMMIT()   asm volatile("cp.async.commit_group;")
#define CPA_WAIT0()    asm volatile("cp.async.wait_group 0;" ::: "memory")

// ---------------------------------------------------------------------------
// fp32 -> fp16 convert (one-time): n4 = count/4
// ---------------------------------------------------------------------------
__global__ void cvt_h(const float* __restrict__ src, __half* __restrict__ dst, int n4)
{
    int i = blockIdx.x*blockDim.x + threadIdx.x;
    if(i < n4){
        float4 f = ((const float4*)src)[i];
        ((__half2*)dst)[2*i  ] = __floats2half2_rn(f.x, f.y);
        ((__half2*)dst)[2*i+1] = __floats2half2_rn(f.z, f.w);
    }
}

// ---------------------------------------------------------------------------
// Projection GEMM: C[4096,1024] = A[4096,1024]h @ W[1024,1024]h^T + b
// grid.z selects (W,bias,C). FP32OUT: fp32 output (final O-proj).
// Otherwise half output; z==2 writes V transposed into [b][e][s].
// BM=128 BN=128 BK=32(half), 8 warps (4m x 2n), cp.async double-buffered.
// Smem rows padded to 40 halves (20 words): conflict-free 32-bit frag loads.
// ---------------------------------------------------------------------------
template<bool FP32OUT>
__global__ void __launch_bounds__(256,2)
proj_h(const __half* __restrict__ A,
       const __half* __restrict__ W0,const __half* __restrict__ W1,const __half* __restrict__ W2,
       const float* __restrict__ b0,const float* __restrict__ b1,const float* __restrict__ b2,
       void* __restrict__ C0,void* __restrict__ C1,void* __restrict__ C2)
{
    constexpr int LD2=20;                       // words per row (40 halves)
    __shared__ unsigned As[2][128*LD2], Bs[2][128*LD2];
    const int z=blockIdx.z;
    const __half* W   = z==0?W0:(z==1?W1:W2);
    const float* bias = z==0?b0:(z==1?b1:b2);
    void*        C    = z==0?C0:(z==1?C1:C2);

    const int tid=threadIdx.x, lane=tid&31, wid=tid>>5;
    const int g=lane>>2, t=lane&3;
    const int wm=wid>>1, wn=wid&1;
    const int m0=blockIdx.y*128, n0=blockIdx.x*128;

    const unsigned as0=(unsigned)__cvta_generic_to_shared(&As[0][0]);
    const unsigned as1=(unsigned)__cvta_generic_to_shared(&As[1][0]);
    const unsigned bs0=(unsigned)__cvta_generic_to_shared(&Bs[0][0]);
    const unsigned bs1=(unsigned)__cvta_generic_to_shared(&Bs[1][0]);

    auto issue=[&](int kt,int buf){
        const unsigned ab=buf?as1:as0, bb=buf?bs1:bs0;
#pragma unroll
        for(int i=0;i<2;i++){
            int idx=tid+i*256, r=idx>>2, cw=(idx&3)<<2;     // cw: word offset
            CPA16(ab+(r*LD2+cw)*4, A+(long)(m0+r)*EE+kt*32+cw*2);
            CPA16(bb+(r*LD2+cw)*4, W+(long)(n0+r)*EE+kt*32+cw*2);
        }
    };

    float acc[2][8][4];
#pragma unroll
    for(int i=0;i<2;i++)
#pragma unroll
        for(int j=0;j<8;j++)
#pragma unroll
            for(int k2=0;k2<4;k2++) acc[i][j][k2]=0.f;

    const int NT=EE/32;   // 32
    issue(0,0); CPA_COMMIT(); CPA_WAIT0(); __syncthreads();
    for(int kt=0;kt<NT;kt++){
        const int buf=kt&1;
        if(kt+1<NT){ issue(kt+1,buf^1); CPA_COMMIT(); }
        const unsigned* Asb=As[buf];
        const unsigned* Bsb=Bs[buf];
#pragma unroll
        for(int kk=0;kk<2;kk++){
            unsigned af[2][4], bf[8][2];
#pragma unroll
            for(int mi=0;mi<2;mi++){
                const int base=(wm*32+mi*16+g)*LD2+kk*8+t;
                af[mi][0]=Asb[base]; af[mi][1]=Asb[base+8*LD2];
                af[mi][2]=Asb[base+4]; af[mi][3]=Asb[base+8*LD2+4];
            }
#pragma unroll
            for(int nj=0;nj<8;nj++){
                const int base=(wn*64+nj*8+g)*LD2+kk*8+t;
                bf[nj][0]=Bsb[base]; bf[nj][1]=Bsb[base+4];
            }
#pragma unroll
            for(int mi=0;mi<2;mi++)
#pragma unroll
                for(int nj=0;nj<8;nj++)
                    mma16(acc[mi][nj],af[mi],bf[nj]);
        }
        if(kt+1<NT){ CPA_WAIT0(); __syncthreads(); }
    }

    const bool vtr = (!FP32OUT) && (z==2);
#pragma unroll
    for(int mi=0;mi<2;mi++){
        const int r0=m0+wm*32+mi*16+g;
#pragma unroll
        for(int nj=0;nj<8;nj++){
            const int col=n0+wn*64+nj*8+2*t;
            float c0=bias[col], c1=bias[col+1];
            float o00=acc[mi][nj][0]+c0, o01=acc[mi][nj][1]+c1;
            float o10=acc[mi][nj][2]+c0, o11=acc[mi][nj][3]+c1;
            if(FP32OUT){
                float* Cf=(float*)C;
                float2 v0={o00,o01}, v1={o10,o11};
                *(float2*)(Cf+(long)r0*EE+col)=v0;
                *(float2*)(Cf+(long)(r0+8)*EE+col)=v1;
            } else if(!vtr){
                __half* Ch=(__half*)C;
                *(__half2*)(Ch+(long)r0*EE+col)=__floats2half2_rn(o00,o01);
                *(__half2*)(Ch+(long)(r0+8)*EE+col)=__floats2half2_rn(o10,o11);
            } else {
                // V transposed: Vt[b][e][s]; r0 = b*2048 + s
                __half* Ch=(__half*)C;
                long base=(long)(r0>>11)*((long)EE*SS)+(r0&2047);
                Ch[base+(long)(col  )*SS  ]=__float2half_rn(o00);
                Ch[base+(long)(col+1)*SS  ]=__float2half_rn(o01);
                Ch[base+(long)(col  )*SS+8]=__float2half_rn(o10);
                Ch[base+(long)(col+1)*SS+8]=__float2half_rn(o11);
            }
        }
    }
}

// ---------------------------------------------------------------------------
// Fused scores + heads-softmax (fp16 in, fp32 acc).
// CTA = (b, q-tile 64, k-tile 32); 8 warps (2m x 4n), warp 32q x 8k.
// Per head: 4 k16 MMA steps. acc holds all 16 heads -> register softmax.
// Smem rows 72 halves (36 words): conflict-free 32-bit frag loads.
// ---------------------------------------------------------------------------
__global__ void __launch_bounds__(256,1)
scores_smax(const __half* __restrict__ Q, const __half* __restrict__ Kh,
            __half* __restrict__ P)
{
    constexpr int LD2=36;
    __shared__ unsigned Qs[2][64*LD2], Ks[2][32*LD2];
    const int tid=threadIdx.x, lane=tid&31, wid=tid>>5;
    const int g=lane>>2, t=lane&3;
    const int wm=wid>>2, wn=wid&3;
    const int b=blockIdx.z, q0=blockIdx.y*64, k0=blockIdx.x*32;
    const __half* Qb=Q +((long)b*SS+q0)*EE;
    const __half* Kb=Kh+((long)b*SS+k0)*EE;

    const unsigned qs0=(unsigned)__cvta_generic_to_shared(&Qs[0][0]);
    const unsigned qs1=(unsigned)__cvta_generic_to_shared(&Qs[1][0]);
    const unsigned ks0=(unsigned)__cvta_generic_to_shared(&Ks[0][0]);
    const unsigned ks1=(unsigned)__cvta_generic_to_shared(&Ks[1][0]);

    auto issue=[&](int h,int buf){
        const unsigned qb=buf?qs1:qs0, kb=buf?ks1:ks0;
#pragma unroll
        for(int i=0;i<2;i++){
            int idx=tid+i*256, r=idx>>3, cw=(idx&7)<<2;
            CPA16(qb+(r*LD2+cw)*4, Qb+(long)r*EE+h*DD+cw*2);
        }
        { int r=tid>>3, cw=(tid&7)<<2;
          CPA16(kb+(r*LD2+cw)*4, Kb+(long)r*EE+h*DD+cw*2); }
    };

    float acc[HH][2][4];
#pragma unroll
    for(int h=0;h<HH;h++)
#pragma unroll
        for(int mi=0;mi<2;mi++)
#pragma unroll
            for(int f=0;f<4;f++) acc[h][mi][f]=0.f;

    issue(0,0); CPA_COMMIT(); CPA_WAIT0(); __syncthreads();
#pragma unroll
    for(int h=0;h<HH;h++){
        const int buf=h&1;
        if(h+1<HH){ issue(h+1,buf^1); CPA_COMMIT(); }
        const unsigned* Qsb=Qs[buf];
        const unsigned* Ksb=Ks[buf];
#pragma unroll
        for(int kk=0;kk<4;kk++){
            unsigned bfr[2];
            const int kb2=(wn*8+g)*LD2+kk*8+t;
            bfr[0]=Ksb[kb2]; bfr[1]=Ksb[kb2+4];
#pragma unroll
            for(int mi=0;mi<2;mi++){
                const int base=(wm*32+mi*16+g)*LD2+kk*8+t;
                unsigned afr[4];
                afr[0]=Qsb[base]; afr[1]=Qsb[base+8*LD2];
                afr[2]=Qsb[base+4]; afr[3]=Qsb[base+8*LD2+4];
                mma16(acc[h][mi],afr,bfr);
            }
        }
        if(h+1<HH){ CPA_WAIT0(); __syncthreads(); }
    }

    // softmax across the 16 heads, per fragment slot (scale 1/8 first)
#pragma unroll
    for(int mi=0;mi<2;mi++)
#pragma unroll
    for(int f=0;f<4;f++){
        float m=-1e30f;
#pragma unroll
        for(int h=0;h<HH;h++){ acc[h][mi][f]*=0.125f; m=fmaxf(m,acc[h][mi][f]); }
        float s=0.f;
#pragma unroll
        for(int h=0;h<HH;h++){ float e=__expf(acc[h][mi][f]-m); acc[h][mi][f]=e; s+=e; }
        const float inv=1.f/s;
#pragma unroll
        for(int h=0;h<HH;h++) acc[h][mi][f]*=inv;
    }

#pragma unroll
    for(int h=0;h<HH;h++){
        __half* Ph=P+((long)(b*HH+h))*QK;
#pragma unroll
        for(int mi=0;mi<2;mi++){
            const int r0=q0+wm*32+mi*16+g;
            const int col=k0+wn*8+2*t;
            *(__half2*)(Ph+(long)r0*SS+col)    =__floats2half2_rn(acc[h][mi][0],acc[h][mi][1]);
            *(__half2*)(Ph+(long)(r0+8)*SS+col)=__floats2half2_rn(acc[h][mi][2],acc[h][mi][3]);
        }
    }
}

// ---------------------------------------------------------------------------
// P @ V per (b,h): AO[2048, h*64..] = P[2048,2048]h @ Vt[h*64..][2048]h^T
// BM=128 BN=64 BK=32(half), 8 warps (4m x 2n), cp.async double-buffered.
// ---------------------------------------------------------------------------
__global__ void __launch_bounds__(256,2)
pv_h(const __half* __restrict__ P, const __half* __restrict__ Vt,
     __half* __restrict__ AO)
{
    constexpr int LD2=20;
    __shared__ unsigned As[2][128*LD2], Vs[2][64*LD2];
    const int tid=threadIdx.x, lane=tid&31, wid=tid>>5;
    const int g=lane>>2, t=lane&3;
    const int wm=wid>>1, wn=wid&1;
    const int z=blockIdx.z, b=z/HH, h=z%HH;
    const int m0=blockIdx.y*128;
    const __half* Pb =P +((long)(b*HH+h))*QK;
    const __half* Vtb=Vt+((long)b*EE+h*DD)*SS;
    __half*       Ob =AO+(long)b*SS*EE+h*DD;

    const unsigned as0=(unsigned)__cvta_generic_to_shared(&As[0][0]);
    const unsigned as1=(unsigned)__cvta_generic_to_shared(&As[1][0]);
    const unsigned vs0=(unsigned)__cvta_generic_to_shared(&Vs[0][0]);
    const unsigned vs1=(unsigned)__cvta_generic_to_shared(&Vs[1][0]);

    auto issue=[&](int kt,int buf){
        const unsigned ab=buf?as1:as0, vb=buf?vs1:vs0;
#pragma unroll
        for(int i=0;i<2;i++){
            int idx=tid+i*256, r=idx>>2, cw=(idx&3)<<2;
            CPA16(ab+(r*LD2+cw)*4, Pb+(long)(m0+r)*SS+kt*32+cw*2);
        }
        { int r=tid>>2, cw=(tid&3)<<2;
          CPA16(vb+(r*LD2+cw)*4, Vtb+(long)r*SS+kt*32+cw*2); }
    };

    float acc[2][4][4];
#pragma unroll
    for(int i=0;i<2;i++)
#pragma unroll
        for(int j=0;j<4;j++)
#pragma unroll
            for(int k2=0;k2<4;k2++) acc[i][j][k2]=0.f;

    const int NT=SS/32;   // 64
    issue(0,0); CPA_COMMIT(); CPA_WAIT0(); __syncthreads();
    for(int kt=0;kt<NT;kt++){
        const int buf=kt&1;
        if(kt+1<NT){ issue(kt+1,buf^1); CPA_COMMIT(); }
        const unsigned* Asb=As[buf];
        const unsigned* Vsb=Vs[buf];
#pragma unroll
        for(int kk=0;kk<2;kk++){
            unsigned af[2][4], bf[4][2];
#pragma unroll
            for(int mi=0;mi<2;mi++){
                const int base=(wm*32+mi*16+g)*LD2+kk*8+t;
                af[mi][0]=Asb[base]; af[mi][1]=Asb[base+8*LD2];
                af[mi][2]=Asb[base+4]; af[mi][3]=Asb[base+8*LD2+4];
            }
#pragma unroll
            for(int nj=0;nj<4;nj++){
                const int base=(wn*32+nj*8+g)*LD2+kk*8+t;
                bf[nj][0]=Vsb[base]; bf[nj][1]=Vsb[base+4];
            }
#pragma unroll
            for(int mi=0;mi<2;mi++)
#pragma unroll
                for(int nj=0;nj<4;nj++)
                    mma16(acc[mi][nj],af[mi],bf[nj]);
        }
        if(kt+1<NT){ CPA_WAIT0(); __syncthreads(); }
    }
#pragma unroll
    for(int mi=0;mi<2;mi++){
        const int r0=m0+wm*32+mi*16+g;
#pragma unroll
        for(int nj=0;nj<4;nj++){
            const int col=wn*32+nj*8+2*t;
            *(__half2*)(Ob+(long)r0*EE+col)    =__floats2half2_rn(acc[mi][nj][0],acc[mi][nj][1]);
            *(__half2*)(Ob+(long)(r0+8)*EE+col)=__floats2half2_rn(acc[mi][nj][2],acc[mi][nj][3]);
        }
    }
}

// ---------------------------------------------------------------------------
extern "C" void kernel_launch(void* const* d_in, const int* in_sizes, int n_in,
                              void* d_out, int out_size)
{
    const float* x  = (const float*)d_in[0];
    const float* Wq = (const float*)d_in[1];
    const float* bq = (const float*)d_in[2];
    const float* Wk = (const float*)d_in[3];
    const float* bk = (const float*)d_in[4];
    const float* Wv = (const float*)d_in[5];
    const float* bv = (const float*)d_in[6];
    const float* Wo = (const float*)d_in[7];
    const float* bo = (const float*)d_in[8];
    float* out = (float*)d_out;

    __half *xh,*wqh,*wkh,*wvh,*woh,*q,*k,*vt,*ao,*p;
    cudaGetSymbolAddress((void**)&xh,  g_xh);
    cudaGetSymbolAddress((void**)&wqh, g_wqh);
    cudaGetSymbolAddress((void**)&wkh, g_wkh);
    cudaGetSymbolAddress((void**)&wvh, g_wvh);
    cudaGetSymbolAddress((void**)&woh, g_woh);
    cudaGetSymbolAddress((void**)&q,   g_q);
    cudaGetSymbolAddress((void**)&k,   g_k);
    cudaGetSymbolAddress((void**)&vt,  g_vt);
    cudaGetSymbolAddress((void**)&ao,  g_ao);
    cudaGetSymbolAddress((void**)&p,   g_p);

    // One-time fp32 -> fp16 conversion of inputs
    cvt_h<<<(MROWS*EE/4+255)/256,256>>>(x,  xh,  MROWS*EE/4);
    cvt_h<<<(EE*EE/4+255)/256,  256>>>(Wq, wqh, EE*EE/4);
    cvt_h<<<(EE*EE/4+255)/256,  256>>>(Wk, wkh, EE*EE/4);
    cvt_h<<<(EE*EE/4+255)/256,  256>>>(Wv, wvh, EE*EE/4);
    cvt_h<<<(EE*EE/4+255)/256,  256>>>(Wo, woh, EE*EE/4);

    dim3 blk(256);

    // Fused Q/K/V projections; z=2 writes V transposed
    dim3 gqkv(EE/128, MROWS/128, 3);
    proj_h<false><<<gqkv,blk>>>(xh, wqh,wkh,wvh, bq,bk,bv, q,k,vt);

    dim3 gsc(SS/32, SS/64, BB);          // (64,32,2)
    scores_smax<<<gsc,blk>>>(q, k, p);

    dim3 gpv(1, SS/128, BB*HH);          // (1,16,32)
    pv_h<<<gpv,blk>>>(p, vt, ao);

    // Output projection -> fp32
    dim3 go(EE/128, MROWS/128, 1);
    proj_h<true><<<go,blk>>>(ao, woh,woh,woh, bo,bo,bo, out,out,out);
}

// round 14
// speedup vs baseline: 1.9195x; 1.4099x over previous
#include <cuda_runtime.h>
#include <cuda_fp16.h>
#include <math.h>

#define BB 2
#define SS 2048
#define EE 1024
#define HH 16
#define DD 64
#define MROWS (BB*SS)            // 4096
#define QK (SS*SS)               // 4194304 per (b,h)

// Scratch (allocation-free rule: __device__ globals), fp16 payloads
__device__ __half g_xh [MROWS*EE];
__device__ __half g_wqh[EE*EE];
__device__ __half g_wkh[EE*EE];
__device__ __half g_wvh[EE*EE];
__device__ __half g_woh[EE*EE];
__device__ __half g_q  [MROWS*EE];
__device__ __half g_k  [MROWS*EE];
__device__ __half g_vt [(long)BB*EE*SS];   // V transposed: [b][e][s]
__device__ __half g_ao [MROWS*EE];
__device__ __half g_p  [134217728];        // [B,H,S,S] probs (256 MB)

// ---------------------------------------------------------------------------
// helpers
// ---------------------------------------------------------------------------
__device__ __forceinline__ void mma16(float* c, const unsigned* a, const unsigned* b){
    asm volatile("mma.sync.aligned.m16n8k16.row.col.f32.f16.f16.f32 "
        "{%0,%1,%2,%3},{%4,%5,%6,%7},{%8,%9},{%0,%1,%2,%3};"
        : "+f"(c[0]),"+f"(c[1]),"+f"(c[2]),"+f"(c[3])
        : "r"(a[0]),"r"(a[1]),"r"(a[2]),"r"(a[3]),"r"(b[0]),"r"(b[1]));
}
__device__ __forceinline__ void ldsm4(unsigned* r, unsigned addr){
    asm volatile("ldmatrix.sync.aligned.m8n8.x4.shared.b16 {%0,%1,%2,%3},[%4];"
        : "=r"(r[0]),"=r"(r[1]),"=r"(r[2]),"=r"(r[3]) : "r"(addr));
}
__device__ __forceinline__ void ldsm2(unsigned* r, unsigned addr){
    asm volatile("ldmatrix.sync.aligned.m8n8.x2.shared.b16 {%0,%1},[%2];"
        : "=r"(r[0]),"=r"(r[1]) : "r"(addr));
}
#define CPA16(dst,src) asm volatile("cp.async.cg.shared.global [%0],[%1],16;"::"r"(dst),"l"(src))
#define CPA_COMMIT()   asm volatile("cp.async.commit_group;")
#define CPA_WAIT0()    asm volatile("cp.async.wait_group 0;" ::: "memory")

// ---------------------------------------------------------------------------
// One fused fp32 -> fp16 conversion for x + the 4 weight matrices.
// Total float4 elements: x 1048576, each W 262144 -> 2097152.
// ---------------------------------------------------------------------------
__global__ void cvt_all(const float* __restrict__ x,
                        const float* __restrict__ wq,const float* __restrict__ wk,
                        const float* __restrict__ wv,const float* __restrict__ wo,
                        __half* __restrict__ xh,
                        __half* __restrict__ wqh,__half* __restrict__ wkh,
                        __half* __restrict__ wvh,__half* __restrict__ woh)
{
    int i = blockIdx.x*blockDim.x + threadIdx.x;
    const float* s; __half* d; int off;
    if(i < 1048576){ s=x; d=xh; off=i; }
    else {
        int j=(i-1048576)>>18; off=(i-1048576)&262143;
        s = j==0?wq:(j==1?wk:(j==2?wv:wo));
        d = j==0?wqh:(j==1?wkh:(j==2?wvh:woh));
    }
    float4 f = ((const float4*)s)[off];
    ((__half2*)d)[2*off  ] = __floats2half2_rn(f.x, f.y);
    ((__half2*)d)[2*off+1] = __floats2half2_rn(f.z, f.w);
}

// ---------------------------------------------------------------------------
// Projection GEMM: C[4096,1024] = A[4096,1024]h @ W[1024,1024]h^T + b
// grid.z selects (W,bias,C). FP32OUT: fp32 output (final O-proj).
// Otherwise half output; z==2 writes V transposed into [b][e][s].
// BM=128 BN=128 BK=32(half), 8 warps (4m x 2n), cp.async + ldmatrix.
// ---------------------------------------------------------------------------
template<bool FP32OUT>
__global__ void __launch_bounds__(256,2)
proj_h(const __half* __restrict__ A,
       const __half* __restrict__ W0,const __half* __restrict__ W1,const __half* __restrict__ W2,
       const float* __restrict__ b0,const float* __restrict__ b1,const float* __restrict__ b2,
       void* __restrict__ C0,void* __restrict__ C1,void* __restrict__ C2)
{
    constexpr int LD2=20;                       // words per row (40 halves)
    __shared__ unsigned As[2][128*LD2], Bs[2][128*LD2];
    const int z=blockIdx.z;
    const __half* W   = z==0?W0:(z==1?W1:W2);
    const float* bias = z==0?b0:(z==1?b1:b2);
    void*        C    = z==0?C0:(z==1?C1:C2);

    const int tid=threadIdx.x, lane=tid&31, wid=tid>>5;
    const int g=lane>>2, t=lane&3;
    const int wm=wid>>1, wn=wid&1;
    const int m0=blockIdx.y*128, n0=blockIdx.x*128;

    const unsigned as0=(unsigned)__cvta_generic_to_shared(&As[0][0]);
    const unsigned as1=(unsigned)__cvta_generic_to_shared(&As[1][0]);
    const unsigned bs0=(unsigned)__cvta_generic_to_shared(&Bs[0][0]);
    const unsigned bs1=(unsigned)__cvta_generic_to_shared(&Bs[1][0]);

    // ldmatrix lane-relative offsets (bytes)
    const unsigned aoff0=((wm*32   +(lane&15))*LD2 + (lane>>4)*4)*4;
    const unsigned aoff1=((wm*32+16+(lane&15))*LD2 + (lane>>4)*4)*4;
    const unsigned boff =((wn*64+(lane&7)+((lane>>4)&1)*8)*LD2 + ((lane>>3)&1)*4)*4;

    auto issue=[&](int kt,int buf){
        const unsigned ab=buf?as1:as0, bb=buf?bs1:bs0;
#pragma unroll
        for(int i=0;i<2;i++){
            int idx=tid+i*256, r=idx>>2, cw=(idx&3)<<2;     // cw: word offset
            CPA16(ab+(r*LD2+cw)*4, A+(long)(m0+r)*EE+kt*32+cw*2);
            CPA16(bb+(r*LD2+cw)*4, W+(long)(n0+r)*EE+kt*32+cw*2);
        }
    };

    float acc[2][8][4];
#pragma unroll
    for(int i=0;i<2;i++)
#pragma unroll
        for(int j=0;j<8;j++)
#pragma unroll
            for(int k2=0;k2<4;k2++) acc[i][j][k2]=0.f;

    const int NT=EE/32;   // 32
    issue(0,0); CPA_COMMIT(); CPA_WAIT0(); __syncthreads();
    for(int kt=0;kt<NT;kt++){
        const int buf=kt&1;
        if(kt+1<NT){ issue(kt+1,buf^1); CPA_COMMIT(); }
        const unsigned ab=buf?as1:as0, bb=buf?bs1:bs0;
#pragma unroll
        for(int kk=0;kk<2;kk++){
            unsigned af[2][4], bf[4][4];
            ldsm4(af[0], ab+aoff0+kk*32);
            ldsm4(af[1], ab+aoff1+kk*32);
#pragma unroll
            for(int pr=0;pr<4;pr++)
                ldsm4(bf[pr], bb+boff+pr*16*LD2*4+kk*32);
#pragma unroll
            for(int mi=0;mi<2;mi++)
#pragma unroll
                for(int nj=0;nj<8;nj++)
                    mma16(acc[mi][nj], af[mi], &bf[nj>>1][(nj&1)*2]);
        }
        if(kt+1<NT){ CPA_WAIT0(); __syncthreads(); }
    }

    const bool vtr = (!FP32OUT) && (z==2);
#pragma unroll
    for(int mi=0;mi<2;mi++){
        const int r0=m0+wm*32+mi*16+g;
#pragma unroll
        for(int nj=0;nj<8;nj++){
            const int col=n0+wn*64+nj*8+2*t;
            float c0=bias[col], c1=bias[col+1];
            float o00=acc[mi][nj][0]+c0, o01=acc[mi][nj][1]+c1;
            float o10=acc[mi][nj][2]+c0, o11=acc[mi][nj][3]+c1;
            if(FP32OUT){
                float* Cf=(float*)C;
                float2 v0={o00,o01}, v1={o10,o11};
                *(float2*)(Cf+(long)r0*EE+col)=v0;
                *(float2*)(Cf+(long)(r0+8)*EE+col)=v1;
            } else if(!vtr){
                __half* Ch=(__half*)C;
                *(__half2*)(Ch+(long)r0*EE+col)=__floats2half2_rn(o00,o01);
                *(__half2*)(Ch+(long)(r0+8)*EE+col)=__floats2half2_rn(o10,o11);
            } else {
                // V transposed: Vt[b][e][s]; r0 = b*2048 + s
                __half* Ch=(__half*)C;
                long base=(long)(r0>>11)*((long)EE*SS)+(r0&2047);
                Ch[base+(long)(col  )*SS  ]=__float2half_rn(o00);
                Ch[base+(long)(col+1)*SS  ]=__float2half_rn(o01);
                Ch[base+(long)(col  )*SS+8]=__float2half_rn(o10);
                Ch[base+(long)(col+1)*SS+8]=__float2half_rn(o11);
            }
        }
    }
}

// ---------------------------------------------------------------------------
// Fused scores + heads-softmax (fp16 in, fp32 acc), ldmatrix fragments.
// CTA = (b, q-tile 64, k-tile 32); 8 warps (2m x 4n), warp 32q x 8k.
// ---------------------------------------------------------------------------
__global__ void __launch_bounds__(256,1)
scores_smax(const __half* __restrict__ Q, const __half* __restrict__ Kh,
            __half* __restrict__ P)
{
    constexpr int LD2=36;
    __shared__ unsigned Qs[2][64*LD2], Ks[2][32*LD2];
    const int tid=threadIdx.x, lane=tid&31, wid=tid>>5;
    const int g=lane>>2, t=lane&3;
    const int wm=wid>>2, wn=wid&3;
    const int b=blockIdx.z, q0=blockIdx.y*64, k0=blockIdx.x*32;
    const __half* Qb=Q +((long)b*SS+q0)*EE;
    const __half* Kb=Kh+((long)b*SS+k0)*EE;

    const unsigned qs0=(unsigned)__cvta_generic_to_shared(&Qs[0][0]);
    const unsigned qs1=(unsigned)__cvta_generic_to_shared(&Qs[1][0]);
    const unsigned ks0=(unsigned)__cvta_generic_to_shared(&Ks[0][0]);
    const unsigned ks1=(unsigned)__cvta_generic_to_shared(&Ks[1][0]);

    const unsigned qoff0=((wm*32   +(lane&15))*LD2 + (lane>>4)*4)*4;
    const unsigned qoff1=((wm*32+16+(lane&15))*LD2 + (lane>>4)*4)*4;
    const unsigned koff =((wn*8+(lane&7))*LD2 + ((lane>>3)&1)*4)*4;  // x2: lanes 0-15

    auto issue=[&](int h,int buf){
        const unsigned qb=buf?qs1:qs0, kb=buf?ks1:ks0;
#pragma unroll
        for(int i=0;i<2;i++){
            int idx=tid+i*256, r=idx>>3, cw=(idx&7)<<2;
            CPA16(qb+(r*LD2+cw)*4, Qb+(long)r*EE+h*DD+cw*2);
        }
        { int r=tid>>3, cw=(tid&7)<<2;
          CPA16(kb+(r*LD2+cw)*4, Kb+(long)r*EE+h*DD+cw*2); }
    };

    float acc[HH][2][4];
#pragma unroll
    for(int h=0;h<HH;h++)
#pragma unroll
        for(int mi=0;mi<2;mi++)
#pragma unroll
            for(int f=0;f<4;f++) acc[h][mi][f]=0.f;

    issue(0,0); CPA_COMMIT(); CPA_WAIT0(); __syncthreads();
#pragma unroll
    for(int h=0;h<HH;h++){
        const int buf=h&1;
        if(h+1<HH){ issue(h+1,buf^1); CPA_COMMIT(); }
        const unsigned qb=buf?qs1:qs0, kb=buf?ks1:ks0;
#pragma unroll
        for(int kk=0;kk<4;kk++){
            unsigned af0[4], af1[4], bfr[2];
            ldsm4(af0, qb+qoff0+kk*32);
            ldsm4(af1, qb+qoff1+kk*32);
            ldsm2(bfr, kb+koff+kk*32);
            mma16(acc[h][0], af0, bfr);
            mma16(acc[h][1], af1, bfr);
        }
        if(h+1<HH){ CPA_WAIT0(); __syncthreads(); }
    }

    // softmax across the 16 heads, per fragment slot (scale 1/8 first)
#pragma unroll
    for(int mi=0;mi<2;mi++)
#pragma unroll
    for(int f=0;f<4;f++){
        float m=-1e30f;
#pragma unroll
        for(int h=0;h<HH;h++){ acc[h][mi][f]*=0.125f; m=fmaxf(m,acc[h][mi][f]); }
        float s=0.f;
#pragma unroll
        for(int h=0;h<HH;h++){ float e=__expf(acc[h][mi][f]-m); acc[h][mi][f]=e; s+=e; }
        const float inv=1.f/s;
#pragma unroll
        for(int h=0;h<HH;h++) acc[h][mi][f]*=inv;
    }

#pragma unroll
    for(int h=0;h<HH;h++){
        __half* Ph=P+((long)(b*HH+h))*QK;
#pragma unroll
        for(int mi=0;mi<2;mi++){
            const int r0=q0+wm*32+mi*16+g;
            const int col=k0+wn*8+2*t;
            *(__half2*)(Ph+(long)r0*SS+col)    =__floats2half2_rn(acc[h][mi][0],acc[h][mi][1]);
            *(__half2*)(Ph+(long)(r0+8)*SS+col)=__floats2half2_rn(acc[h][mi][2],acc[h][mi][3]);
        }
    }
}

// ---------------------------------------------------------------------------
// P @ V per (b,h): AO[2048, h*64..] = P[2048,2048]h @ Vt[h*64..][2048]h^T
// BM=128 BN=64 BK=32(half), 8 warps (4m x 2n), cp.async + ldmatrix.
// ---------------------------------------------------------------------------
__global__ void __launch_bounds__(256,2)
pv_h(const __half* __restrict__ P, const __half* __restrict__ Vt,
     __half* __restrict__ AO)
{
    constexpr int LD2=20;
    __shared__ unsigned As[2][128*LD2], Vs[2][64*LD2];
    const int tid=threadIdx.x, lane=tid&31, wid=tid>>5;
    const int g=lane>>2, t=lane&3;
    const int wm=wid>>1, wn=wid&1;
    const int z=blockIdx.z, b=z/HH, h=z%HH;
    const int m0=blockIdx.y*128;
    const __half* Pb =P +((long)(b*HH+h))*QK;
    const __half* Vtb=Vt+((long)b*EE+h*DD)*SS;
    __half*       Ob =AO+(long)b*SS*EE+h*DD;

    const unsigned as0=(unsigned)__cvta_generic_to_shared(&As[0][0]);
    const unsigned as1=(unsigned)__cvta_generic_to_shared(&As[1][0]);
    const unsigned vs0=(unsigned)__cvta_generic_to_shared(&Vs[0][0]);
    const unsigned vs1=(unsigned)__cvta_generic_to_shared(&Vs[1][0]);

    const unsigned aoff0=((wm*32   +(lane&15))*LD2 + (lane>>4)*4)*4;
    const unsigned aoff1=((wm*32+16+(lane&15))*LD2 + (lane>>4)*4)*4;
    const unsigned boff =((wn*32+(lane&7)+((lane>>4)&1)*8)*LD2 + ((lane>>3)&1)*4)*4;

    auto issue=[&](int kt,int buf){
        const unsigned ab=buf?as1:as0, vb=buf?vs1:vs0;
#pragma unroll
        for(int i=0;i<2;i++){
            int idx=tid+i*256, r=idx>>2, cw=(idx&3)<<2;
            CPA16(ab+(r*LD2+cw)*4, Pb+(long)(m0+r)*SS+kt*32+cw*2);
        }
        { int r=tid>>2, cw=(tid&3)<<2;
          CPA16(vb+(r*LD2+cw)*4, Vtb+(long)r*SS+kt*32+cw*2); }
    };

    float acc[2][4][4];
#pragma unroll
    for(int i=0;i<2;i++)
#pragma unroll
        for(int j=0;j<4;j++)
#pragma unroll
            for(int k2=0;k2<4;k2++) acc[i][j][k2]=0.f;

    const int NT=SS/32;   // 64
    issue(0,0); CPA_COMMIT(); CPA_WAIT0(); __syncthreads();
    for(int kt=0;kt<NT;kt++){
        const int buf=kt&1;
        if(kt+1<NT){ issue(kt+1,buf^1); CPA_COMMIT(); }
        const unsigned ab=buf?as1:as0, vb=buf?vs1:vs0;
#pragma unroll
        for(int kk=0;kk<2;kk++){
            unsigned af[2][4], bf[2][4];
            ldsm4(af[0], ab+aoff0+kk*32);
            ldsm4(af[1], ab+aoff1+kk*32);
            ldsm4(bf[0], vb+boff+kk*32);
            ldsm4(bf[1], vb+boff+16*LD2*4+kk*32);
#pragma unroll
            for(int mi=0;mi<2;mi++)
#pragma unroll
                for(int nj=0;nj<4;nj++)
                    mma16(acc[mi][nj], af[mi], &bf[nj>>1][(nj&1)*2]);
        }
        if(kt+1<NT){ CPA_WAIT0(); __syncthreads(); }
    }
#pragma unroll
    for(int mi=0;mi<2;mi++){
        const int r0=m0+wm*32+mi*16+g;
#pragma unroll
        for(int nj=0;nj<4;nj++){
            const int col=wn*32+nj*8+2*t;
            *(__half2*)(Ob+(long)r0*EE+col)    =__floats2half2_rn(acc[mi][nj][0],acc[mi][nj][1]);
            *(__half2*)(Ob+(long)(r0+8)*EE+col)=__floats2half2_rn(acc[mi][nj][2],acc[mi][nj][3]);
        }
    }
}

// ---------------------------------------------------------------------------
extern "C" void kernel_launch(void* const* d_in, const int* in_sizes, int n_in,
                              void* d_out, int out_size)
{
    const float* x  = (const float*)d_in[0];
    const float* Wq = (const float*)d_in[1];
    const float* bq = (const float*)d_in[2];
    const float* Wk = (const float*)d_in[3];
    const float* bk = (const float*)d_in[4];
    const float* Wv = (const float*)d_in[5];
    const float* bv = (const float*)d_in[6];
    const float* Wo = (const float*)d_in[7];
    const float* bo = (const float*)d_in[8];
    float* out = (float*)d_out;

    __half *xh,*wqh,*wkh,*wvh,*woh,*q,*k,*vt,*ao,*p;
    cudaGetSymbolAddress((void**)&xh,  g_xh);
    cudaGetSymbolAddress((void**)&wqh, g_wqh);
    cudaGetSymbolAddress((void**)&wkh, g_wkh);
    cudaGetSymbolAddress((void**)&wvh, g_wvh);
    cudaGetSymbolAddress((void**)&woh, g_woh);
    cudaGetSymbolAddress((void**)&q,   g_q);
    cudaGetSymbolAddress((void**)&k,   g_k);
    cudaGetSymbolAddress((void**)&vt,  g_vt);
    cudaGetSymbolAddress((void**)&ao,  g_ao);
    cudaGetSymbolAddress((void**)&p,   g_p);

    dim3 blk(256);

    // One fused fp32 -> fp16 conversion pass
    cvt_all<<<8192,256>>>(x, Wq,Wk,Wv,Wo, xh, wqh,wkh,wvh,woh);

    // Fused Q/K/V projections; z=2 writes V transposed
    dim3 gqkv(EE/128, MROWS/128, 3);
    proj_h<false><<<gqkv,blk>>>(xh, wqh,wkh,wvh, bq,bk,bv, q,k,vt);

    dim3 gsc(SS/32, SS/64, BB);          // (64,32,2)
    scores_smax<<<gsc,blk>>>(q, k, p);

    dim3 gpv(1, SS/128, BB*HH);          // (1,16,32)
    pv_h<<<gpv,blk>>>(p, vt, ao);

    // Output projection -> fp32
    dim3 go(EE/128, MROWS/128, 1);
    proj_h<true><<<go,blk>>>(ao, woh,woh,woh, bo,bo,bo, out,out,out);
}